// round 7
// baseline (speedup 1.0000x reference)
#include <cuda_runtime.h>

// Differential box-counting fractal dimension, 512x512 f32, 64x64 windows
// stride 4 -> 113x113. One block per OUTPUT ROW (113 blocks = one wave).
// 1024 threads/block; P1 loads explicitly batched for MLP=8.

#define OH 113

__global__ __launch_bounds__(1024, 1)
void fd_kernel(const float* __restrict__ img, float* __restrict__ out)
{
    // L0: 16x128 4x4-tile max/min. L1: even rows (8x127). L2: rows {0,4,8,12}
    // (4x125). L3: rows {0,8} (2x121). Cols padded to 128.
    __shared__ float M0[16][128], N0[16][128];
    __shared__ float M1[8][128],  N1[8][128];
    __shared__ float M2[4][128],  N2[4][128];
    __shared__ float M3[2][128],  N3[2][128];
    __shared__ float cs0[128], cs1[128], cs2[128];

    const int tid = threadIdx.x;
    const int gi  = blockIdx.x;        // output row 0..112
    const int R0  = 4 * gi;            // top pixel row

    // ---- P1: 4x4 pixel-tile max/min, 16x128 tiles, 2 tiles/thread ----
    // Tile A: (r, c) with r = tid>>7 (0..7), c = tid&127.
    // Tile B: (r+8, c). Load ALL 8 float4 first (one latency exposure).
    {
        const int r = tid >> 7, c = tid & 127;
        const float* pA = img + (R0 + 4 * r) * 512 + 4 * c;
        const float* pB = pA + 32 * 512;
        float4 v0 = *reinterpret_cast<const float4*>(pA);
        float4 v1 = *reinterpret_cast<const float4*>(pA + 512);
        float4 v2 = *reinterpret_cast<const float4*>(pA + 1024);
        float4 v3 = *reinterpret_cast<const float4*>(pA + 1536);
        float4 w0 = *reinterpret_cast<const float4*>(pB);
        float4 w1 = *reinterpret_cast<const float4*>(pB + 512);
        float4 w2 = *reinterpret_cast<const float4*>(pB + 1024);
        float4 w3 = *reinterpret_cast<const float4*>(pB + 1536);

        float mxA = fmaxf(fmaxf(v0.x, v0.y), fmaxf(v0.z, v0.w));
        float mnA = fminf(fminf(v0.x, v0.y), fminf(v0.z, v0.w));
        mxA = fmaxf(mxA, fmaxf(fmaxf(v1.x, v1.y), fmaxf(v1.z, v1.w)));
        mnA = fminf(mnA, fminf(fminf(v1.x, v1.y), fminf(v1.z, v1.w)));
        mxA = fmaxf(mxA, fmaxf(fmaxf(v2.x, v2.y), fmaxf(v2.z, v2.w)));
        mnA = fminf(mnA, fminf(fminf(v2.x, v2.y), fminf(v2.z, v2.w)));
        mxA = fmaxf(mxA, fmaxf(fmaxf(v3.x, v3.y), fmaxf(v3.z, v3.w)));
        mnA = fminf(mnA, fminf(fminf(v3.x, v3.y), fminf(v3.z, v3.w)));

        float mxB = fmaxf(fmaxf(w0.x, w0.y), fmaxf(w0.z, w0.w));
        float mnB = fminf(fminf(w0.x, w0.y), fminf(w0.z, w0.w));
        mxB = fmaxf(mxB, fmaxf(fmaxf(w1.x, w1.y), fmaxf(w1.z, w1.w)));
        mnB = fminf(mnB, fminf(fminf(w1.x, w1.y), fminf(w1.z, w1.w)));
        mxB = fmaxf(mxB, fmaxf(fmaxf(w2.x, w2.y), fmaxf(w2.z, w2.w)));
        mnB = fminf(mnB, fminf(fminf(w2.x, w2.y), fminf(w2.z, w2.w)));
        mxB = fmaxf(mxB, fmaxf(fmaxf(w3.x, w3.y), fmaxf(w3.z, w3.w)));
        mnB = fminf(mnB, fminf(fminf(w3.x, w3.y), fminf(w3.z, w3.w)));

        M0[r][c]     = mxA;  N0[r][c]     = mnA;
        M0[r + 8][c] = mxB;  N0[r + 8][c] = mnB;
    }
    __syncthreads();

    // ---- P2: L1, even rows only: a<8 (row 2a), c<127 — single pass ----
    if (tid < 8 * 127) {
        const int a = tid / 127, c = tid % 127;
        const int r = 2 * a;
        M1[a][c] = fmaxf(fmaxf(M0[r][c],   M0[r+1][c]),
                         fmaxf(M0[r][c+1], M0[r+1][c+1]));
        N1[a][c] = fminf(fminf(N0[r][c],   N0[r+1][c]),
                         fminf(N0[r][c+1], N0[r+1][c+1]));
    }
    __syncthreads();

    // ---- P3: L2, rows {0,4,8,12} stored a2<4, c<125 ----
    if (tid < 4 * 125) {
        const int a2 = tid / 125, c = tid % 125;
        const int a1 = 2 * a2;
        M2[a2][c] = fmaxf(fmaxf(M1[a1][c],   M1[a1+1][c]),
                          fmaxf(M1[a1][c+2], M1[a1+1][c+2]));
        N2[a2][c] = fminf(fminf(N1[a1][c],   N1[a1+1][c]),
                          fminf(N1[a1][c+2], N1[a1+1][c+2]));
    }
    __syncthreads();

    // ---- P4+P5 fused: L3 max/min AND column sums (622 items, one pass) ----
    if (tid < 242) {
        // L3 rows {0,8}: j<2, c<121; uses L2 stored rows 2j,2j+1, cols c,c+4
        const int j = tid / 121, c = tid % 121;
        const int a = 2 * j;
        M3[j][c] = fmaxf(fmaxf(M2[a][c],   M2[a+1][c]),
                         fmaxf(M2[a][c+4], M2[a+1][c+4]));
        N3[j][c] = fminf(fminf(N2[a][c],   N2[a+1][c]),
                         fminf(N2[a][c+4], N2[a+1][c+4]));
    } else if (tid < 370) {
        const int c = tid - 242;               // c < 128
        float s = 0.f;
        #pragma unroll
        for (int r = 0; r < 16; r++) s += M0[r][c] - N0[r][c];
        cs0[c] = s;
    } else if (tid < 497) {
        const int c = tid - 370;               // c < 127
        float s = 0.f;
        #pragma unroll
        for (int a = 0; a < 8; a++) s += M1[a][c] - N1[a][c];
        cs1[c] = s;
    } else if (tid < 622) {
        const int c = tid - 497;               // c < 125
        float s = 0.f;
        #pragma unroll
        for (int a = 0; a < 4; a++) s += M2[a][c] - N2[a][c];
        cs2[c] = s;
    }
    __syncthreads();

    // ---- P6: per-window horizontal sums + regression (113 threads) ----
    if (tid < OH) {
        const int wj = tid;
        float d4 = 0.f, d8 = 0.f, d16 = 0.f;
        #pragma unroll
        for (int t = 0; t < 16; t++) d4  += cs0[wj + t];
        #pragma unroll
        for (int b = 0; b < 8;  b++) d8  += cs1[wj + 2 * b];
        #pragma unroll
        for (int b = 0; b < 4;  b++) d16 += cs2[wj + 4 * b];

        const float d32 = (M3[0][wj]   - N3[0][wj])
                        + (M3[1][wj]   - N3[1][wj])
                        + (M3[0][wj+8] - N3[0][wj+8])
                        + (M3[1][wj+8] - N3[1][wj+8]);
        const float d64 = fmaxf(fmaxf(M3[0][wj], M3[1][wj]),
                                fmaxf(M3[0][wj+8], M3[1][wj+8]))
                        - fminf(fminf(N3[0][wj], N3[1][wj]),
                                fminf(N3[0][wj+8], N3[1][wj+8]));

        const float ls0 = 4.15888308336f;   // ln 64
        const float ls1 = 3.46573590280f;   // ln 32
        const float ls2 = 2.77258872224f;   // ln 16
        const float ls3 = 2.07944154168f;   // ln 8
        const float ls4 = 1.38629436112f;   // ln 4
        const float S2  = ls0*ls0 + ls1*ls1 + ls2*ls2 + ls3*ls3 + ls4*ls4;
        const float num = ls0 * __logf(d64) + ls1 * __logf(d32)
                        + ls2 * __logf(d16) + ls3 * __logf(d8)
                        + ls4 * __logf(d4);
        out[gi * OH + wj] = -num / S2;
    }
}

extern "C" void kernel_launch(void* const* d_in, const int* in_sizes, int n_in,
                              void* d_out, int out_size)
{
    const float* img = (const float*)d_in[0];   // (1,1,512,512) f32
    float* out = (float*)d_out;                 // (1,1,113,113) f32
    fd_kernel<<<OH, 1024>>>(img, out);
}

// round 8
// speedup vs baseline: 1.3527x; 1.3527x over previous
#include <cuda_runtime.h>

// Differential box-counting fractal dimension, 512x512 f32, 64x64 windows
// stride 4 -> 113x113. One block per OUTPUT ROW (113 blocks = one wave).
// 3 phases / 2 barriers: P1 builds packed (max,min) 4x4-tile grid D0;
// phase B computes ALL level sums directly from D0 (levels are contiguous
// L0 regions); P6 does per-window horizontal sums + regression.

#define OH 113

__global__ __launch_bounds__(1024, 1)
void fd_kernel(const float* __restrict__ img, float* __restrict__ out)
{
    __shared__ float2 D0[16][128];     // (max, min) of each 4x4 pixel tile
    __shared__ float2 D3[2][128];      // L3 quadrant (max, min), rows {0,8}, c<121
    __shared__ float  cs0[128], cs1[128], cs2[128];

    const int tid = threadIdx.x;
    const int gi  = blockIdx.x;        // output row 0..112
    const int R0  = 4 * gi;            // top pixel row

    // ---- P1: 4x4 pixel-tile max/min, 16x128 tiles, 2 tiles/thread,
    //      all 8 float4 loads batched (one latency exposure) ----
    {
        const int r = tid >> 7, c = tid & 127;
        const float* pA = img + (R0 + 4 * r) * 512 + 4 * c;
        const float* pB = pA + 32 * 512;
        float4 v0 = *reinterpret_cast<const float4*>(pA);
        float4 v1 = *reinterpret_cast<const float4*>(pA + 512);
        float4 v2 = *reinterpret_cast<const float4*>(pA + 1024);
        float4 v3 = *reinterpret_cast<const float4*>(pA + 1536);
        float4 w0 = *reinterpret_cast<const float4*>(pB);
        float4 w1 = *reinterpret_cast<const float4*>(pB + 512);
        float4 w2 = *reinterpret_cast<const float4*>(pB + 1024);
        float4 w3 = *reinterpret_cast<const float4*>(pB + 1536);

        float mxA = fmaxf(fmaxf(v0.x, v0.y), fmaxf(v0.z, v0.w));
        float mnA = fminf(fminf(v0.x, v0.y), fminf(v0.z, v0.w));
        mxA = fmaxf(mxA, fmaxf(fmaxf(v1.x, v1.y), fmaxf(v1.z, v1.w)));
        mnA = fminf(mnA, fminf(fminf(v1.x, v1.y), fminf(v1.z, v1.w)));
        mxA = fmaxf(mxA, fmaxf(fmaxf(v2.x, v2.y), fmaxf(v2.z, v2.w)));
        mnA = fminf(mnA, fminf(fminf(v2.x, v2.y), fminf(v2.z, v2.w)));
        mxA = fmaxf(mxA, fmaxf(fmaxf(v3.x, v3.y), fmaxf(v3.z, v3.w)));
        mnA = fminf(mnA, fminf(fminf(v3.x, v3.y), fminf(v3.z, v3.w)));

        float mxB = fmaxf(fmaxf(w0.x, w0.y), fmaxf(w0.z, w0.w));
        float mnB = fminf(fminf(w0.x, w0.y), fminf(w0.z, w0.w));
        mxB = fmaxf(mxB, fmaxf(fmaxf(w1.x, w1.y), fmaxf(w1.z, w1.w)));
        mnB = fminf(mnB, fminf(fminf(w1.x, w1.y), fminf(w1.z, w1.w)));
        mxB = fmaxf(mxB, fmaxf(fmaxf(w2.x, w2.y), fmaxf(w2.z, w2.w)));
        mnB = fminf(mnB, fminf(fminf(w2.x, w2.y), fminf(w2.z, w2.w)));
        mxB = fmaxf(mxB, fmaxf(fmaxf(w3.x, w3.y), fmaxf(w3.z, w3.w)));
        mnB = fminf(mnB, fminf(fminf(w3.x, w3.y), fminf(w3.z, w3.w)));

        D0[r][c]     = make_float2(mxA, mnA);
        D0[r + 8][c] = make_float2(mxB, mnB);
    }
    __syncthreads();

    // ---- Phase B: everything directly from D0 ----
    if (tid < 128) {
        // cs0[c] = sum over 16 rows of (max - min)
        const int c = tid;
        float s = 0.f;
        #pragma unroll
        for (int r = 0; r < 16; r++) {
            const float2 v = D0[r][c];
            s += v.x - v.y;
        }
        cs0[c] = s;
    } else if (tid < 255) {
        // cs1[c] = sum over a<8 of diff of 2x2 L0 block (rows 2a..2a+1, cols c..c+1)
        const int c = tid - 128;       // c < 127
        float s = 0.f;
        #pragma unroll
        for (int a = 0; a < 8; a++) {
            const float2 v00 = D0[2*a][c],   v01 = D0[2*a][c+1];
            const float2 v10 = D0[2*a+1][c], v11 = D0[2*a+1][c+1];
            const float m = fmaxf(fmaxf(v00.x, v01.x), fmaxf(v10.x, v11.x));
            const float n = fminf(fminf(v00.y, v01.y), fminf(v10.y, v11.y));
            s += m - n;
        }
        cs1[c] = s;
    } else if (tid >= 256 && tid < 381) {
        // cs2[c] = sum over a<4 of diff of 4x4 L0 block (rows 4a..4a+3, cols c..c+3)
        const int c = tid - 256;       // c < 125
        float s = 0.f;
        #pragma unroll
        for (int a = 0; a < 4; a++) {
            float m = -3.0e38f, n = 3.0e38f;
            #pragma unroll
            for (int dr = 0; dr < 4; dr++) {
                #pragma unroll
                for (int dc = 0; dc < 4; dc++) {
                    const float2 v = D0[4*a + dr][c + dc];
                    m = fmaxf(m, v.x);
                    n = fminf(n, v.y);
                }
            }
            s += m - n;
        }
        cs2[c] = s;
    } else if (tid >= 512 && tid < 754) {
        // L3 quadrants: j<2 (rows 8j..8j+7), c<121 (cols c..c+7), 8x8 L0 block
        const int idx = tid - 512;     // < 242
        const int j = idx / 121, c = idx % 121;
        float m = -3.0e38f, n = 3.0e38f;
        #pragma unroll
        for (int dr = 0; dr < 8; dr++) {
            #pragma unroll
            for (int dc = 0; dc < 8; dc++) {
                const float2 v = D0[8*j + dr][c + dc];
                m = fmaxf(m, v.x);
                n = fminf(n, v.y);
            }
        }
        D3[j][c] = make_float2(m, n);
    }
    __syncthreads();

    // ---- P6: per-window horizontal sums + regression (113 threads) ----
    if (tid < OH) {
        const int wj = tid;
        float d4 = 0.f, d8 = 0.f, d16 = 0.f;
        #pragma unroll
        for (int t = 0; t < 16; t++) d4  += cs0[wj + t];
        #pragma unroll
        for (int b = 0; b < 8;  b++) d8  += cs1[wj + 2 * b];
        #pragma unroll
        for (int b = 0; b < 4;  b++) d16 += cs2[wj + 4 * b];

        const float2 q00 = D3[0][wj],     q01 = D3[0][wj + 8];
        const float2 q10 = D3[1][wj],     q11 = D3[1][wj + 8];
        const float d32 = (q00.x - q00.y) + (q01.x - q01.y)
                        + (q10.x - q10.y) + (q11.x - q11.y);
        const float d64 = fmaxf(fmaxf(q00.x, q01.x), fmaxf(q10.x, q11.x))
                        - fminf(fminf(q00.y, q01.y), fminf(q10.y, q11.y));

        const float ls0 = 4.15888308336f;   // ln 64
        const float ls1 = 3.46573590280f;   // ln 32
        const float ls2 = 2.77258872224f;   // ln 16
        const float ls3 = 2.07944154168f;   // ln 8
        const float ls4 = 1.38629436112f;   // ln 4
        const float S2  = ls0*ls0 + ls1*ls1 + ls2*ls2 + ls3*ls3 + ls4*ls4;
        const float num = ls0 * __logf(d64) + ls1 * __logf(d32)
                        + ls2 * __logf(d16) + ls3 * __logf(d8)
                        + ls4 * __logf(d4);
        out[gi * OH + wj] = -num / S2;
    }
}

extern "C" void kernel_launch(void* const* d_in, const int* in_sizes, int n_in,
                              void* d_out, int out_size)
{
    const float* img = (const float*)d_in[0];   // (1,1,512,512) f32
    float* out = (float*)d_out;                 // (1,1,113,113) f32
    fd_kernel<<<OH, 1024>>>(img, out);
}